// round 10
// baseline (speedup 1.0000x reference)
#include <cuda_runtime.h>
#include <math.h>

#define NN 100000
#define NG 64
#define D  128
#define EMAX 2600000   // E + 8*NN padding headroom

typedef unsigned long long ull;

// -------- scratch (device globals; no runtime allocation) --------
__device__ float g_h   [(size_t)(NN + 8) * D]; // dinv-scaled GEMM output
__device__ float g_agg [(size_t)NN * D];       // layer-2 aggregated output (pool input)
__device__ float g_elu [(size_t)NN * D];       // elu(layer-1 agg) = layer-2 GEMM input
__device__ float g_dinv[NN];                   // deg^{-1/2}
__device__ int   g_cnti[NN];                   // per-dst edge counts (re-zeroed by k_scan)
__device__ int   g_off [NN + 1];               // CSR offsets (8-aligned region starts)
__device__ int   g_cur [NN];                   // fill cursors; after k_fill = actual end
__device__ __align__(16) int g_srcs[EMAX];     // CSR adjacency
__device__ float g_pool[NG * D];
__device__ float g_cnt [NG];

// ---------------- CSR build ----------------
__global__ void k_count(const int* __restrict__ ei, int E) {
    int e = blockIdx.x * blockDim.x + threadIdx.x;
    if (e >= E) return;
    unsigned dst = (unsigned)ei[(size_t)E + e];
    if (dst < NN) atomicAdd(&g_cnti[dst], 1);
}

#define SCAN_T 1024
// single block: exclusive scan of 8-aligned region sizes -> off/cur, dinv,
// re-zero g_cnti, zero pool accumulators. (No pad writes: pads never read.)
__global__ void k_scan() {
    __shared__ int ssum[SCAN_T];
    int t = threadIdx.x;

    for (int i = t; i < NG * D; i += SCAN_T) g_pool[i] = 0.f;
    if (t < NG) g_cnt[t] = 0.f;

    int per = (NN + SCAN_T - 1) / SCAN_T;
    int lo = t * per, hi = lo + per; if (hi > NN) hi = NN;
    int s = 0;
    for (int i = lo; i < hi; i++) s += (g_cnti[i] + 7) & ~7;
    ssum[t] = s;
    __syncthreads();
    for (int ofs = 1; ofs < SCAN_T; ofs <<= 1) {
        int v = (t >= ofs) ? ssum[t - ofs] : 0;
        __syncthreads();
        ssum[t] += v;
        __syncthreads();
    }
    int run = (t == 0) ? 0 : ssum[t - 1];
    for (int i = lo; i < hi; i++) {
        int c  = g_cnti[i];
        g_off[i] = run;
        g_cur[i] = run;
        g_dinv[i] = rsqrtf((float)c + 1.0f);   // +1 self loop
        g_cnti[i] = 0;                          // ready for next replay
        run += (c + 7) & ~7;
    }
    if (t == SCAN_T - 1) g_off[NN] = run;
}

__global__ void k_fill(const int* __restrict__ ei, int E) {
    int e = blockIdx.x * blockDim.x + threadIdx.x;
    if (e >= E) return;
    unsigned src = (unsigned)ei[e];
    unsigned dst = (unsigned)ei[(size_t)E + e];
    if (src >= NN || dst >= NN) return;
    int pos = atomicAdd(&g_cur[dst], 1);   // after kernel: g_cur[d] = off[d]+deg(d)
    if (pos < EMAX) g_srcs[pos] = (int)src;
}

// ---------------- SGEMM (f32x2) : g_h = dinv * (X @ W) --------------------
#define BM 128
#define BN 128
#define BKK 32
#define KTILES (D / BKK)   // 4

#define FMA2(d, a, b) asm("fma.rn.f32x2 %0, %1, %2, %3;" : "=l"(d) : "l"(a), "l"(b), "l"(d))

__device__ __forceinline__
void gemm_body(const float* __restrict__ X, const float* __restrict__ W) {
    __shared__ float sA [BKK][BM];       // 16 KB, [k][m]
    __shared__ float sBd[BKK][2 * BN];   // 32 KB, duplicated cols

    int tid = threadIdx.x;
    int tm  = tid >> 4;
    int tn  = tid & 15;
    int m0  = blockIdx.x * BM;

    int arow = tid >> 1;
    int ak0  = (tid & 1) * 16;

    ull acc[4][8];
#pragma unroll
    for (int i = 0; i < 4; i++)
#pragma unroll
        for (int j = 0; j < 8; j++) acc[i][j] = 0ull;

    float4 ra[4];
    {
        int row = m0 + arow;
        const float4* xr = (const float4*)(X + (size_t)row * D) + (ak0 >> 2);
#pragma unroll
        for (int i = 0; i < 4; i++)
            ra[i] = (row < NN) ? __ldg(&xr[i]) : make_float4(0.f, 0.f, 0.f, 0.f);
    }

    for (int t = 0; t < KTILES; t++) {
#pragma unroll
        for (int i = 0; i < 4; i++) {
            sA[ak0 + i * 4 + 0][arow] = ra[i].x;
            sA[ak0 + i * 4 + 1][arow] = ra[i].y;
            sA[ak0 + i * 4 + 2][arow] = ra[i].z;
            sA[ak0 + i * 4 + 3][arow] = ra[i].w;
        }
        {
            const float4* wg = (const float4*)(W + (size_t)t * BKK * D);
#pragma unroll
            for (int i = 0; i < 4; i++) {
                float4 v = __ldg(&wg[tid + 256 * i]);
                int p = tid + 256 * i;
                int k = p >> 5;
                int c = (p & 31) * 4;
                *(float4*)&sBd[k][2 * c]     = make_float4(v.x, v.x, v.y, v.y);
                *(float4*)&sBd[k][2 * c + 4] = make_float4(v.z, v.z, v.w, v.w);
            }
        }
        __syncthreads();

        if (t + 1 < KTILES) {
            int kt = (t + 1) * BKK;
            int row = m0 + arow;
            const float4* xr = (const float4*)(X + (size_t)row * D + kt) + (ak0 >> 2);
#pragma unroll
            for (int i = 0; i < 4; i++)
                ra[i] = (row < NN) ? __ldg(&xr[i]) : make_float4(0.f, 0.f, 0.f, 0.f);
        }

#pragma unroll
        for (int k = 0; k < BKK; k++) {
            ulonglong2 alo = *(ulonglong2*)&sA[k][tm * 4];
            ulonglong2 ahi = *(ulonglong2*)&sA[k][64 + tm * 4];
            ull ap[4] = {alo.x, alo.y, ahi.x, ahi.y};
            ull bp[8];
#pragma unroll
            for (int jj = 0; jj < 8; jj++)
                bp[jj] = *(ull*)&sBd[k][2 * (tn + 16 * jj)];
#pragma unroll
            for (int r = 0; r < 4; r++)
#pragma unroll
                for (int jj = 0; jj < 8; jj++)
                    FMA2(acc[r][jj], ap[r], bp[jj]);
        }
        __syncthreads();
    }

    // epilogue: scale by dinv[row], store
#pragma unroll
    for (int r = 0; r < 4; r++) {
        int row0 = m0 + (r >> 1) * 64 + tm * 4 + (r & 1) * 2;
        int row1 = row0 + 1;
        bool ok0 = row0 < NN, ok1 = row1 < NN;
        float d0 = ok0 ? g_dinv[row0] : 0.f;
        float d1 = ok1 ? g_dinv[row1] : 0.f;
        float* h0 = g_h + (size_t)row0 * D;
        float* h1 = g_h + (size_t)row1 * D;
#pragma unroll
        for (int jj = 0; jj < 8; jj++) {
            ull v = acc[r][jj];
            int col = tn + 16 * jj;
            if (ok0) h0[col] = d0 * __uint_as_float((unsigned)v);
            if (ok1) h1[col] = d1 * __uint_as_float((unsigned)(v >> 32));
        }
    }
}

__global__ __launch_bounds__(256, 2)
void k_gemm_l1(const float* __restrict__ X, const float* __restrict__ W) {
    gemm_body(X, W);
}

__global__ __launch_bounds__(256, 2)
void k_gemm_l2(const float* __restrict__ W) {
    gemm_body(g_elu, W);
}

// ---------------- CSR gather (warp/node, 8-wide main + scalar tail) ------
// g_h holds hs = dinv*h.  out = bias + dinv[n] * ( hs[n] + sum_s hs[s] )
template<bool DO_ELU>
__global__ void k_gather(const float* __restrict__ bias) {
    int node = (blockIdx.x * blockDim.x + threadIdx.x) >> 5;
    int lane = threadIdx.x & 31;
    if (node >= NN) return;

    float dv = g_dinv[node];
    float4 acc = __ldg((const float4*)(g_h + (size_t)node * D) + lane); // self = hs[n]

    int j   = g_off[node];     // 8-aligned region start
    int end = g_cur[node];     // actual end (off + degree)
    if (end > EMAX) end = EMAX;

    for (; j + 8 <= end; j += 8) {
        int4 sa = __ldg((const int4*)(g_srcs + j));
        int4 sb = __ldg((const int4*)(g_srcs + j + 4));
        float4 v0 = __ldg((const float4*)(g_h + (size_t)sa.x * D) + lane);
        float4 v1 = __ldg((const float4*)(g_h + (size_t)sa.y * D) + lane);
        float4 v2 = __ldg((const float4*)(g_h + (size_t)sa.z * D) + lane);
        float4 v3 = __ldg((const float4*)(g_h + (size_t)sa.w * D) + lane);
        float4 v4 = __ldg((const float4*)(g_h + (size_t)sb.x * D) + lane);
        float4 v5 = __ldg((const float4*)(g_h + (size_t)sb.y * D) + lane);
        float4 v6 = __ldg((const float4*)(g_h + (size_t)sb.z * D) + lane);
        float4 v7 = __ldg((const float4*)(g_h + (size_t)sb.w * D) + lane);
        acc.x += ((v0.x + v1.x) + (v2.x + v3.x)) + ((v4.x + v5.x) + (v6.x + v7.x));
        acc.y += ((v0.y + v1.y) + (v2.y + v3.y)) + ((v4.y + v5.y) + (v6.y + v7.y));
        acc.z += ((v0.z + v1.z) + (v2.z + v3.z)) + ((v4.z + v5.z) + (v6.z + v7.z));
        acc.w += ((v0.w + v1.w) + (v2.w + v3.w)) + ((v4.w + v5.w) + (v6.w + v7.w));
    }
    for (; j < end; j++) {
        int s = __ldg(&g_srcs[j]);
        float4 v = __ldg((const float4*)(g_h + (size_t)s * D) + lane);
        acc.x += v.x; acc.y += v.y; acc.z += v.z; acc.w += v.w;
    }

    float4 b = __ldg((const float4*)bias + lane);
    acc.x = b.x + dv * acc.x;
    acc.y = b.y + dv * acc.y;
    acc.z = b.z + dv * acc.z;
    acc.w = b.w + dv * acc.w;

    if (DO_ELU) {
        acc.x = acc.x > 0.f ? acc.x : expm1f(acc.x);
        acc.y = acc.y > 0.f ? acc.y : expm1f(acc.y);
        acc.z = acc.z > 0.f ? acc.z : expm1f(acc.z);
        acc.w = acc.w > 0.f ? acc.w : expm1f(acc.w);
        ((float4*)(g_elu + (size_t)node * D))[lane] = acc;
    } else {
        ((float4*)(g_agg + (size_t)node * D))[lane] = acc;
    }
}

// ---------------- pooling ----------------
#define NPB 256
__global__ void k_pool(const int* __restrict__ batch) {
    int f = threadIdx.x;
    int start = blockIdx.x * NPB;
    if (start >= NN) return;
    int end = start + NPB; if (end > NN) end = NN;

    float acc = 0.f;
    int cur = batch[start];
    if ((unsigned)cur >= NG) cur = 0;
    for (int n = start; n < end; n++) {
        int b = batch[n];
        if ((unsigned)b >= NG) b = 0;
        if (b != cur) {
            atomicAdd(&g_pool[cur * D + f], acc);
            acc = 0.f; cur = b;
        }
        acc += g_agg[(size_t)n * D + f];
    }
    atomicAdd(&g_pool[cur * D + f], acc);

    if (f == 0) {
        float c = 0.f;
        int cur2 = batch[start];
        if ((unsigned)cur2 >= NG) cur2 = 0;
        for (int n = start; n < end; n++) {
            int b = batch[n];
            if ((unsigned)b >= NG) b = 0;
            if (b != cur2) { atomicAdd(&g_cnt[cur2], c); c = 0.f; cur2 = b; }
            c += 1.0f;
        }
        atomicAdd(&g_cnt[cur2], c);
    }
}

// ---------------- final MLP + log_softmax ----------------
__global__ void k_mlp(const float* __restrict__ fc1W, const float* __restrict__ fc1b,
                      const float* __restrict__ fc2W, const float* __restrict__ fc2b,
                      float* __restrict__ out) {
    int g = blockIdx.x;
    int lane = threadIdx.x;
    __shared__ float mean[D];
    __shared__ float m1[20];
    __shared__ float z[10];
    __shared__ float lse;

    float cnt = fmaxf(g_cnt[g], 1.0f);
    for (int k = lane; k < D; k += 32) mean[k] = g_pool[g * D + k] / cnt;
    __syncwarp();

    if (lane < 20) {
        float s = fc1b[lane];
        for (int k = 0; k < D; k++) s = fmaf(mean[k], fc1W[k * 20 + lane], s);
        m1[lane] = fmaxf(s, 0.0f);
    }
    __syncwarp();

    if (lane < 10) {
        float s = fc2b[lane];
        for (int k = 0; k < 20; k++) s = fmaf(m1[k], fc2W[k * 10 + lane], s);
        z[lane] = s;
    }
    __syncwarp();

    if (lane == 0) {
        float mx = z[0];
        for (int j = 1; j < 10; j++) mx = fmaxf(mx, z[j]);
        float s = 0.f;
        for (int j = 0; j < 10; j++) s += expf(z[j] - mx);
        lse = mx + logf(s);
    }
    __syncwarp();

    if (lane < 10) out[g * 10 + lane] = z[lane] - lse;
}

// ---------------- launch ----------------
extern "C" void kernel_launch(void* const* d_in, const int* in_sizes, int n_in,
                              void* d_out, int out_size) {
    int ix = -1, iei = -1, ib = -1, iW[2] = {-1, -1}, ibias[2] = {-1, -1};
    int if1W = -1, if1b = -1, if2W = -1, if2b = -1;
    int nW = 0, nbias = 0;
    for (int i = 0; i < n_in; i++) {
        int s = in_sizes[i];
        if      (s == NN * D)            ix = i;
        else if (s == NN)                ib = i;
        else if (s == D * D && nW < 2)   iW[nW++] = i;
        else if (s == D && nbias < 2)    ibias[nbias++] = i;
        else if (s == D * 20)            if1W = i;
        else if (s == 20)                if1b = i;
        else if (s == 20 * 10)           if2W = i;
        else if (s == 10)                if2b = i;
        else if (s > NN)                 iei = i;
    }
    bool ok = (ix >= 0 && iei >= 0 && ib >= 0 && nW == 2 && nbias == 2 &&
               if1W >= 0 && if1b >= 0 && if2W >= 0 && if2b >= 0);
    if (!ok) {
        ix = 0; iei = 1; ib = 2; iW[0] = 3; ibias[0] = 4; iW[1] = 5; ibias[1] = 6;
        if1W = 7; if1b = 8; if2W = 9; if2b = 10;
    }

    const float* x     = (const float*)d_in[ix];
    const int*   ei    = (const int*)d_in[iei];
    const int*   batch = (const int*)d_in[ib];
    const float* W1   = (const float*)d_in[iW[0]];
    const float* b1   = (const float*)d_in[ibias[0]];
    const float* W2   = (const float*)d_in[iW[1]];
    const float* b2   = (const float*)d_in[ibias[1]];
    const float* fc1W = (const float*)d_in[if1W];
    const float* fc1b = (const float*)d_in[if1b];
    const float* fc2W = (const float*)d_in[if2W];
    const float* fc2b = (const float*)d_in[if2b];
    float* out = (float*)d_out;

    int E = in_sizes[iei] / 2;

    const int T = 256;
    int nb_edges  = (E + T - 1) / T;
    int nb_gemm   = (NN + BM - 1) / BM;
    int nb_gather = (int)(((size_t)NN * 32 + T - 1) / T);
    int nb_pool   = (NN + NPB - 1) / NPB;

    k_count<<<nb_edges, T>>>(ei, E);                  // 0
    k_scan<<<1, SCAN_T>>>();                          // 1
    k_fill<<<nb_edges, T>>>(ei, E);                   // 2
    k_gemm_l1<<<nb_gemm, 256>>>(x, W1);               // 3  <- profiled
    k_gather<true><<<nb_gather, T>>>(b1);             // 4  -> g_elu
    k_gemm_l2<<<nb_gemm, 256>>>(W2);                  // 5
    k_gather<false><<<nb_gather, T>>>(b2);            // 6  -> g_agg
    k_pool<<<nb_pool, D>>>(batch);                    // 7
    k_mlp<<<NG, 32>>>(fc1W, fc1b, fc2W, fc2b, out);   // 8
}

// round 11
// speedup vs baseline: 1.2882x; 1.2882x over previous
#include <cuda_runtime.h>
#include <math.h>

#define NN 100000
#define NG 64
#define D  128
#define EMAX 2000000

typedef unsigned long long ull;

// -------- scratch (device globals; no runtime allocation) --------
__device__ float g_h   [(size_t)NN * D];   // dinv-scaled GEMM output (hs = dinv*XW)
__device__ float g_agg [(size_t)NN * D];   // layer-2 aggregated output (pool input)
__device__ float g_elu [(size_t)NN * D];   // elu(layer-1 agg) = layer-2 GEMM input
__device__ float g_dinv[NN];               // deg^{-1/2}
__device__ int   g_cnti[NN];               // per-dst edge counts (re-zeroed by k_scan)
__device__ int   g_off [NN + 1];           // CSR offsets (exact)
__device__ int   g_cur [NN];               // fill cursors
__device__ int   g_srcs[EMAX];             // CSR adjacency (src per edge, grouped by dst)
__device__ float g_pool[NG * D];
__device__ float g_cnt [NG];

// ---------------- CSR build ----------------
__global__ void k_count(const int* __restrict__ ei, int E) {
    int e = blockIdx.x * blockDim.x + threadIdx.x;
    if (e >= E) return;
    unsigned dst = (unsigned)ei[(size_t)E + e];
    if (dst < NN) atomicAdd(&g_cnti[dst], 1);
}

#define SCAN_T 1024
// single block: exact exclusive scan -> off/cur, dinv, re-zero cnti, zero pool.
__global__ void k_scan() {
    __shared__ int ssum[SCAN_T];
    int t = threadIdx.x;

    for (int i = t; i < NG * D; i += SCAN_T) g_pool[i] = 0.f;
    if (t < NG) g_cnt[t] = 0.f;

    int per = (NN + SCAN_T - 1) / SCAN_T;
    int lo = t * per, hi = lo + per; if (hi > NN) hi = NN;
    int s = 0;
    for (int i = lo; i < hi; i++) s += g_cnti[i];
    ssum[t] = s;
    __syncthreads();
    for (int ofs = 1; ofs < SCAN_T; ofs <<= 1) {
        int v = (t >= ofs) ? ssum[t - ofs] : 0;
        __syncthreads();
        ssum[t] += v;
        __syncthreads();
    }
    int run = (t == 0) ? 0 : ssum[t - 1];
    for (int i = lo; i < hi; i++) {
        int c = g_cnti[i];
        g_off[i] = run;
        g_cur[i] = run;
        g_dinv[i] = rsqrtf((float)c + 1.0f);   // +1 self loop
        g_cnti[i] = 0;                          // ready for next replay
        run += c;
    }
    if (t == SCAN_T - 1) g_off[NN] = run;
}

__global__ void k_fill(const int* __restrict__ ei, int E) {
    int e = blockIdx.x * blockDim.x + threadIdx.x;
    if (e >= E) return;
    unsigned src = (unsigned)ei[e];
    unsigned dst = (unsigned)ei[(size_t)E + e];
    if (src >= NN || dst >= NN) return;
    int pos = atomicAdd(&g_cur[dst], 1);
    if (pos < EMAX) g_srcs[pos] = (int)src;
}

// ---------------- SGEMM (f32x2) : g_h = dinv * (X @ W) --------------------
#define BM 128
#define BN 128
#define BKK 32
#define KTILES (D / BKK)   // 4

#define FMA2(d, a, b) asm("fma.rn.f32x2 %0, %1, %2, %3;" : "=l"(d) : "l"(a), "l"(b), "l"(d))

__device__ __forceinline__
void gemm_body(const float* __restrict__ X, const float* __restrict__ W) {
    __shared__ float sA [BKK][BM];       // 16 KB, [k][m]
    __shared__ float sBd[BKK][2 * BN];   // 32 KB, duplicated cols

    int tid = threadIdx.x;
    int tm  = tid >> 4;
    int tn  = tid & 15;
    int m0  = blockIdx.x * BM;

    int arow = tid >> 1;
    int ak0  = (tid & 1) * 16;

    ull acc[4][8];
#pragma unroll
    for (int i = 0; i < 4; i++)
#pragma unroll
        for (int j = 0; j < 8; j++) acc[i][j] = 0ull;

    float4 ra[4];
    {
        int row = m0 + arow;
        const float4* xr = (const float4*)(X + (size_t)row * D) + (ak0 >> 2);
#pragma unroll
        for (int i = 0; i < 4; i++)
            ra[i] = (row < NN) ? __ldg(&xr[i]) : make_float4(0.f, 0.f, 0.f, 0.f);
    }

    for (int t = 0; t < KTILES; t++) {
#pragma unroll
        for (int i = 0; i < 4; i++) {
            sA[ak0 + i * 4 + 0][arow] = ra[i].x;
            sA[ak0 + i * 4 + 1][arow] = ra[i].y;
            sA[ak0 + i * 4 + 2][arow] = ra[i].z;
            sA[ak0 + i * 4 + 3][arow] = ra[i].w;
        }
        {
            const float4* wg = (const float4*)(W + (size_t)t * BKK * D);
#pragma unroll
            for (int i = 0; i < 4; i++) {
                float4 v = __ldg(&wg[tid + 256 * i]);
                int p = tid + 256 * i;
                int k = p >> 5;
                int c = (p & 31) * 4;
                *(float4*)&sBd[k][2 * c]     = make_float4(v.x, v.x, v.y, v.y);
                *(float4*)&sBd[k][2 * c + 4] = make_float4(v.z, v.z, v.w, v.w);
            }
        }
        __syncthreads();

        if (t + 1 < KTILES) {
            int kt = (t + 1) * BKK;
            int row = m0 + arow;
            const float4* xr = (const float4*)(X + (size_t)row * D + kt) + (ak0 >> 2);
#pragma unroll
            for (int i = 0; i < 4; i++)
                ra[i] = (row < NN) ? __ldg(&xr[i]) : make_float4(0.f, 0.f, 0.f, 0.f);
        }

#pragma unroll
        for (int k = 0; k < BKK; k++) {
            ulonglong2 alo = *(ulonglong2*)&sA[k][tm * 4];
            ulonglong2 ahi = *(ulonglong2*)&sA[k][64 + tm * 4];
            ull ap[4] = {alo.x, alo.y, ahi.x, ahi.y};
            ull bp[8];
#pragma unroll
            for (int jj = 0; jj < 8; jj++)
                bp[jj] = *(ull*)&sBd[k][2 * (tn + 16 * jj)];
#pragma unroll
            for (int r = 0; r < 4; r++)
#pragma unroll
                for (int jj = 0; jj < 8; jj++)
                    FMA2(acc[r][jj], ap[r], bp[jj]);
        }
        __syncthreads();
    }

    // epilogue: scale by dinv[row], store
#pragma unroll
    for (int r = 0; r < 4; r++) {
        int row0 = m0 + (r >> 1) * 64 + tm * 4 + (r & 1) * 2;
        int row1 = row0 + 1;
        bool ok0 = row0 < NN, ok1 = row1 < NN;
        float d0 = ok0 ? g_dinv[row0] : 0.f;
        float d1 = ok1 ? g_dinv[row1] : 0.f;
        float* h0 = g_h + (size_t)row0 * D;
        float* h1 = g_h + (size_t)row1 * D;
#pragma unroll
        for (int jj = 0; jj < 8; jj++) {
            ull v = acc[r][jj];
            int col = tn + 16 * jj;
            if (ok0) h0[col] = d0 * __uint_as_float((unsigned)v);
            if (ok1) h1[col] = d1 * __uint_as_float((unsigned)(v >> 32));
        }
    }
}

__global__ __launch_bounds__(256, 2)
void k_gemm_l1(const float* __restrict__ X, const float* __restrict__ W) {
    gemm_body(X, W);
}

__global__ __launch_bounds__(256, 2)
void k_gemm_l2(const float* __restrict__ W) {
    gemm_body(g_elu, W);
}

// ---------------- CSR gather (warp/node, R7-proven structure) -------------
// g_h holds hs = dinv*h.  out = bias + dinv[n] * ( hs[n] + sum_s hs[s] )
template<bool DO_ELU>
__global__ void k_gather(const float* __restrict__ bias) {
    int node = (blockIdx.x * blockDim.x + threadIdx.x) >> 5;
    int lane = threadIdx.x & 31;
    if (node >= NN) return;

    float dv = g_dinv[node];
    float4 acc = __ldg((const float4*)(g_h + (size_t)node * D) + lane); // self = hs[n]

    int j   = g_off[node];
    int end = g_off[node + 1];
    for (; j + 4 <= end; j += 4) {
        int s0 = __ldg(&g_srcs[j + 0]);
        int s1 = __ldg(&g_srcs[j + 1]);
        int s2 = __ldg(&g_srcs[j + 2]);
        int s3 = __ldg(&g_srcs[j + 3]);
        float4 v0 = __ldg((const float4*)(g_h + (size_t)s0 * D) + lane);
        float4 v1 = __ldg((const float4*)(g_h + (size_t)s1 * D) + lane);
        float4 v2 = __ldg((const float4*)(g_h + (size_t)s2 * D) + lane);
        float4 v3 = __ldg((const float4*)(g_h + (size_t)s3 * D) + lane);
        acc.x += (v0.x + v1.x) + (v2.x + v3.x);
        acc.y += (v0.y + v1.y) + (v2.y + v3.y);
        acc.z += (v0.z + v1.z) + (v2.z + v3.z);
        acc.w += (v0.w + v1.w) + (v2.w + v3.w);
    }
    for (; j < end; j++) {
        int s = __ldg(&g_srcs[j]);
        float4 v = __ldg((const float4*)(g_h + (size_t)s * D) + lane);
        acc.x += v.x; acc.y += v.y; acc.z += v.z; acc.w += v.w;
    }

    float4 b = __ldg((const float4*)bias + lane);
    acc.x = b.x + dv * acc.x;
    acc.y = b.y + dv * acc.y;
    acc.z = b.z + dv * acc.z;
    acc.w = b.w + dv * acc.w;

    if (DO_ELU) {
        acc.x = acc.x > 0.f ? acc.x : expm1f(acc.x);
        acc.y = acc.y > 0.f ? acc.y : expm1f(acc.y);
        acc.z = acc.z > 0.f ? acc.z : expm1f(acc.z);
        acc.w = acc.w > 0.f ? acc.w : expm1f(acc.w);
        ((float4*)(g_elu + (size_t)node * D))[lane] = acc;
    } else {
        ((float4*)(g_agg + (size_t)node * D))[lane] = acc;
    }
}

// ---------------- pooling ----------------
#define NPB 256
__global__ void k_pool(const int* __restrict__ batch) {
    int f = threadIdx.x;
    int start = blockIdx.x * NPB;
    if (start >= NN) return;
    int end = start + NPB; if (end > NN) end = NN;

    float acc = 0.f;
    int cur = batch[start];
    if ((unsigned)cur >= NG) cur = 0;
    for (int n = start; n < end; n++) {
        int b = batch[n];
        if ((unsigned)b >= NG) b = 0;
        if (b != cur) {
            atomicAdd(&g_pool[cur * D + f], acc);
            acc = 0.f; cur = b;
        }
        acc += g_agg[(size_t)n * D + f];
    }
    atomicAdd(&g_pool[cur * D + f], acc);

    if (f == 0) {
        float c = 0.f;
        int cur2 = batch[start];
        if ((unsigned)cur2 >= NG) cur2 = 0;
        for (int n = start; n < end; n++) {
            int b = batch[n];
            if ((unsigned)b >= NG) b = 0;
            if (b != cur2) { atomicAdd(&g_cnt[cur2], c); c = 0.f; cur2 = b; }
            c += 1.0f;
        }
        atomicAdd(&g_cnt[cur2], c);
    }
}

// ---------------- final MLP + log_softmax ----------------
__global__ void k_mlp(const float* __restrict__ fc1W, const float* __restrict__ fc1b,
                      const float* __restrict__ fc2W, const float* __restrict__ fc2b,
                      float* __restrict__ out) {
    int g = blockIdx.x;
    int lane = threadIdx.x;
    __shared__ float mean[D];
    __shared__ float m1[20];
    __shared__ float z[10];
    __shared__ float lse;

    float cnt = fmaxf(g_cnt[g], 1.0f);
    for (int k = lane; k < D; k += 32) mean[k] = g_pool[g * D + k] / cnt;
    __syncwarp();

    if (lane < 20) {
        float s = fc1b[lane];
        for (int k = 0; k < D; k++) s = fmaf(mean[k], fc1W[k * 20 + lane], s);
        m1[lane] = fmaxf(s, 0.0f);
    }
    __syncwarp();

    if (lane < 10) {
        float s = fc2b[lane];
        for (int k = 0; k < 20; k++) s = fmaf(m1[k], fc2W[k * 10 + lane], s);
        z[lane] = s;
    }
    __syncwarp();

    if (lane == 0) {
        float mx = z[0];
        for (int j = 1; j < 10; j++) mx = fmaxf(mx, z[j]);
        float s = 0.f;
        for (int j = 0; j < 10; j++) s += expf(z[j] - mx);
        lse = mx + logf(s);
    }
    __syncwarp();

    if (lane < 10) out[g * 10 + lane] = z[lane] - lse;
}

// ---------------- launch ----------------
extern "C" void kernel_launch(void* const* d_in, const int* in_sizes, int n_in,
                              void* d_out, int out_size) {
    int ix = -1, iei = -1, ib = -1, iW[2] = {-1, -1}, ibias[2] = {-1, -1};
    int if1W = -1, if1b = -1, if2W = -1, if2b = -1;
    int nW = 0, nbias = 0;
    for (int i = 0; i < n_in; i++) {
        int s = in_sizes[i];
        if      (s == NN * D)            ix = i;
        else if (s == NN)                ib = i;
        else if (s == D * D && nW < 2)   iW[nW++] = i;
        else if (s == D && nbias < 2)    ibias[nbias++] = i;
        else if (s == D * 20)            if1W = i;
        else if (s == 20)                if1b = i;
        else if (s == 20 * 10)           if2W = i;
        else if (s == 10)                if2b = i;
        else if (s > NN)                 iei = i;
    }
    bool ok = (ix >= 0 && iei >= 0 && ib >= 0 && nW == 2 && nbias == 2 &&
               if1W >= 0 && if1b >= 0 && if2W >= 0 && if2b >= 0);
    if (!ok) {
        ix = 0; iei = 1; ib = 2; iW[0] = 3; ibias[0] = 4; iW[1] = 5; ibias[1] = 6;
        if1W = 7; if1b = 8; if2W = 9; if2b = 10;
    }

    const float* x     = (const float*)d_in[ix];
    const int*   ei    = (const int*)d_in[iei];
    const int*   batch = (const int*)d_in[ib];
    const float* W1   = (const float*)d_in[iW[0]];
    const float* b1   = (const float*)d_in[ibias[0]];
    const float* W2   = (const float*)d_in[iW[1]];
    const float* b2   = (const float*)d_in[ibias[1]];
    const float* fc1W = (const float*)d_in[if1W];
    const float* fc1b = (const float*)d_in[if1b];
    const float* fc2W = (const float*)d_in[if2W];
    const float* fc2b = (const float*)d_in[if2b];
    float* out = (float*)d_out;

    int E = in_sizes[iei] / 2;

    const int T = 256;
    int nb_edges  = (E + T - 1) / T;
    int nb_gemm   = (NN + BM - 1) / BM;
    int nb_gather = (int)(((size_t)NN * 32 + T - 1) / T);
    int nb_pool   = (NN + NPB - 1) / NPB;

    k_count<<<nb_edges, T>>>(ei, E);                  // 0
    k_scan<<<1, SCAN_T>>>();                          // 1
    k_fill<<<nb_edges, T>>>(ei, E);                   // 2
    k_gemm_l1<<<nb_gemm, 256>>>(x, W1);               // 3  <- profiled (clock control)
    k_gather<true><<<nb_gather, T>>>(b1);             // 4  -> g_elu
    k_gemm_l2<<<nb_gemm, 256>>>(W2);                  // 5
    k_gather<false><<<nb_gather, T>>>(b2);            // 6  -> g_agg
    k_pool<<<nb_pool, D>>>(batch);                    // 7
    k_mlp<<<NG, 32>>>(fc1W, fc1b, fc2W, fc2b, out);   // 8
}

// round 12
// speedup vs baseline: 1.3492x; 1.0473x over previous
#include <cuda_runtime.h>
#include <cuda_fp16.h>
#include <math.h>

#define NN 100000
#define NG 64
#define D  128
#define EMAX 2000000

typedef unsigned long long ull;

// -------- scratch (device globals; no runtime allocation) --------
__device__ __half g_h [(size_t)NN * D];    // GEMM output, fp16 (gather payload)
__device__ float g_agg [(size_t)NN * D];   // layer-2 aggregated output (pool input)
__device__ float g_elu [(size_t)NN * D];   // elu(layer-1 agg) = layer-2 GEMM input, fp32
__device__ float g_dinv[NN];               // deg^{-1/2}
__device__ int   g_cnti[NN];               // per-dst edge counts (re-zeroed by k_scan)
__device__ int   g_off [NN + 1];           // CSR offsets (exact)
__device__ int   g_cur [NN];               // fill cursors
__device__ int   g_srcs[EMAX];             // CSR adjacency (src per edge, grouped by dst)
__device__ float g_pool[NG * D];
__device__ float g_cnt [NG];

#define SCAN_T 1024
// single block: exact exclusive scan -> off/cur, dinv, re-zero cnti, zero pool.
__global__ void k_scan() {
    __shared__ int ssum[SCAN_T];
    int t = threadIdx.x;

    for (int i = t; i < NG * D; i += SCAN_T) g_pool[i] = 0.f;
    if (t < NG) g_cnt[t] = 0.f;

    int per = (NN + SCAN_T - 1) / SCAN_T;
    int lo = t * per, hi = lo + per; if (hi > NN) hi = NN;
    int s = 0;
    for (int i = lo; i < hi; i++) s += g_cnti[i];
    ssum[t] = s;
    __syncthreads();
    for (int ofs = 1; ofs < SCAN_T; ofs <<= 1) {
        int v = (t >= ofs) ? ssum[t - ofs] : 0;
        __syncthreads();
        ssum[t] += v;
        __syncthreads();
    }
    int run = (t == 0) ? 0 : ssum[t - 1];
    for (int i = lo; i < hi; i++) {
        int c = g_cnti[i];
        g_off[i] = run;
        g_cur[i] = run;
        g_dinv[i] = rsqrtf((float)c + 1.0f);   // +1 self loop
        g_cnti[i] = 0;                          // ready for next replay
        run += c;
    }
    if (t == SCAN_T - 1) g_off[NN] = run;
}

__global__ void k_fill(const int* __restrict__ ei, int E) {
    int e = blockIdx.x * blockDim.x + threadIdx.x;
    if (e >= E) return;
    unsigned src = (unsigned)ei[e];
    unsigned dst = (unsigned)ei[(size_t)E + e];
    if (src >= NN || dst >= NN) return;
    int pos = atomicAdd(&g_cur[dst], 1);
    if (pos < EMAX) g_srcs[pos] = (int)src;
}

// ---------------- SGEMM (f32x2) : g_h = half(X @ W) -----------------------
#define BM 128
#define BN 128
#define BKK 32
#define KTILES (D / BKK)   // 4

#define FMA2(d, a, b) asm("fma.rn.f32x2 %0, %1, %2, %3;" : "=l"(d) : "l"(a), "l"(b), "l"(d))

template<bool DO_COUNT>
__device__ __forceinline__
void gemm_body(const float* __restrict__ X, const float* __restrict__ W,
               const int* __restrict__ ei, int E) {
    __shared__ float sA [BKK][BM];       // 16 KB, [k][m]
    __shared__ float sBd[BKK][2 * BN];   // 32 KB, duplicated cols

    int tid = threadIdx.x;
    int tm  = tid >> 4;
    int tn  = tid & 15;
    int m0  = blockIdx.x * BM;

    int arow = tid >> 1;
    int ak0  = (tid & 1) * 16;

    // fused edge-degree count (layer-1 only) — overlaps with first tile loads
    if (DO_COUNT) {
        int stride = gridDim.x * blockDim.x;
        for (int e = blockIdx.x * blockDim.x + tid; e < E; e += stride) {
            unsigned dst = (unsigned)__ldg(&ei[(size_t)E + e]);
            if (dst < NN) atomicAdd(&g_cnti[dst], 1);
        }
    }

    ull acc[4][8];
#pragma unroll
    for (int i = 0; i < 4; i++)
#pragma unroll
        for (int j = 0; j < 8; j++) acc[i][j] = 0ull;

    float4 ra[4];
    {
        int row = m0 + arow;
        const float4* xr = (const float4*)(X + (size_t)row * D) + (ak0 >> 2);
#pragma unroll
        for (int i = 0; i < 4; i++)
            ra[i] = (row < NN) ? __ldg(&xr[i]) : make_float4(0.f, 0.f, 0.f, 0.f);
    }

    for (int t = 0; t < KTILES; t++) {
#pragma unroll
        for (int i = 0; i < 4; i++) {
            sA[ak0 + i * 4 + 0][arow] = ra[i].x;
            sA[ak0 + i * 4 + 1][arow] = ra[i].y;
            sA[ak0 + i * 4 + 2][arow] = ra[i].z;
            sA[ak0 + i * 4 + 3][arow] = ra[i].w;
        }
        {
            const float4* wg = (const float4*)(W + (size_t)t * BKK * D);
#pragma unroll
            for (int i = 0; i < 4; i++) {
                float4 v = __ldg(&wg[tid + 256 * i]);
                int p = tid + 256 * i;
                int k = p >> 5;
                int c = (p & 31) * 4;
                *(float4*)&sBd[k][2 * c]     = make_float4(v.x, v.x, v.y, v.y);
                *(float4*)&sBd[k][2 * c + 4] = make_float4(v.z, v.z, v.w, v.w);
            }
        }
        __syncthreads();

        if (t + 1 < KTILES) {
            int kt = (t + 1) * BKK;
            int row = m0 + arow;
            const float4* xr = (const float4*)(X + (size_t)row * D + kt) + (ak0 >> 2);
#pragma unroll
            for (int i = 0; i < 4; i++)
                ra[i] = (row < NN) ? __ldg(&xr[i]) : make_float4(0.f, 0.f, 0.f, 0.f);
        }

#pragma unroll
        for (int k = 0; k < BKK; k++) {
            ulonglong2 alo = *(ulonglong2*)&sA[k][tm * 4];
            ulonglong2 ahi = *(ulonglong2*)&sA[k][64 + tm * 4];
            ull ap[4] = {alo.x, alo.y, ahi.x, ahi.y};
            ull bp[8];
#pragma unroll
            for (int jj = 0; jj < 8; jj++)
                bp[jj] = *(ull*)&sBd[k][2 * (tn + 16 * jj)];
#pragma unroll
            for (int r = 0; r < 4; r++)
#pragma unroll
                for (int jj = 0; jj < 8; jj++)
                    FMA2(acc[r][jj], ap[r], bp[jj]);
        }
        __syncthreads();
    }

    // epilogue: store fp16
#pragma unroll
    for (int r = 0; r < 4; r++) {
        int row0 = m0 + (r >> 1) * 64 + tm * 4 + (r & 1) * 2;
        int row1 = row0 + 1;
        bool ok0 = row0 < NN, ok1 = row1 < NN;
        __half* h0 = g_h + (size_t)row0 * D;
        __half* h1 = g_h + (size_t)row1 * D;
#pragma unroll
        for (int jj = 0; jj < 8; jj++) {
            ull v = acc[r][jj];
            int col = tn + 16 * jj;
            if (ok0) h0[col] = __float2half(__uint_as_float((unsigned)v));
            if (ok1) h1[col] = __float2half(__uint_as_float((unsigned)(v >> 32)));
        }
    }
}

__global__ __launch_bounds__(256, 2)
void k_gemm_l1(const float* __restrict__ X, const float* __restrict__ W,
               const int* __restrict__ ei, int E) {
    gemm_body<true>(X, W, ei, E);
}

__global__ __launch_bounds__(256, 2)
void k_gemm_l2(const float* __restrict__ W) {
    gemm_body<false>(g_elu, W, nullptr, 0);
}

// ---------------- CSR gather (warp/node, fp16 rows) -----------------------
// out = bias + dinv[n] * ( dinv[n]*h[n] + sum_s dinv[s]*h[s] )
__device__ __forceinline__ float4 ld_row_h(int s, int lane) {
    uint2 u = __ldg((const uint2*)(g_h + (size_t)s * D) + lane);  // 4 halves
    float2 a = __half22float2(*(__half2*)&u.x);
    float2 b = __half22float2(*(__half2*)&u.y);
    return make_float4(a.x, a.y, b.x, b.y);
}

template<bool DO_ELU>
__global__ void k_gather(const float* __restrict__ bias) {
    int node = (blockIdx.x * blockDim.x + threadIdx.x) >> 5;
    int lane = threadIdx.x & 31;
    if (node >= NN) return;

    float dv = g_dinv[node];
    float4 self = ld_row_h(node, lane);
    float4 acc = make_float4(self.x * dv, self.y * dv, self.z * dv, self.w * dv);

    int j   = g_off[node];
    int end = g_off[node + 1];
    for (; j + 4 <= end; j += 4) {
        int s0 = __ldg(&g_srcs[j + 0]);
        int s1 = __ldg(&g_srcs[j + 1]);
        int s2 = __ldg(&g_srcs[j + 2]);
        int s3 = __ldg(&g_srcs[j + 3]);
        float d0 = __ldg(&g_dinv[s0]);
        float d1 = __ldg(&g_dinv[s1]);
        float d2 = __ldg(&g_dinv[s2]);
        float d3 = __ldg(&g_dinv[s3]);
        float4 v0 = ld_row_h(s0, lane);
        float4 v1 = ld_row_h(s1, lane);
        float4 v2 = ld_row_h(s2, lane);
        float4 v3 = ld_row_h(s3, lane);
        acc.x += v0.x * d0 + v1.x * d1 + v2.x * d2 + v3.x * d3;
        acc.y += v0.y * d0 + v1.y * d1 + v2.y * d2 + v3.y * d3;
        acc.z += v0.z * d0 + v1.z * d1 + v2.z * d2 + v3.z * d3;
        acc.w += v0.w * d0 + v1.w * d1 + v2.w * d2 + v3.w * d3;
    }
    for (; j < end; j++) {
        int s = __ldg(&g_srcs[j]);
        float d = __ldg(&g_dinv[s]);
        float4 v = ld_row_h(s, lane);
        acc.x += v.x * d; acc.y += v.y * d;
        acc.z += v.z * d; acc.w += v.w * d;
    }

    float4 b = __ldg((const float4*)bias + lane);
    acc.x = b.x + dv * acc.x;
    acc.y = b.y + dv * acc.y;
    acc.z = b.z + dv * acc.z;
    acc.w = b.w + dv * acc.w;

    if (DO_ELU) {
        acc.x = acc.x > 0.f ? acc.x : expm1f(acc.x);
        acc.y = acc.y > 0.f ? acc.y : expm1f(acc.y);
        acc.z = acc.z > 0.f ? acc.z : expm1f(acc.z);
        acc.w = acc.w > 0.f ? acc.w : expm1f(acc.w);
        ((float4*)(g_elu + (size_t)node * D))[lane] = acc;
    } else {
        ((float4*)(g_agg + (size_t)node * D))[lane] = acc;
    }
}

// ---------------- pooling ----------------
#define NPB 256
__global__ void k_pool(const int* __restrict__ batch) {
    int f = threadIdx.x;
    int start = blockIdx.x * NPB;
    if (start >= NN) return;
    int end = start + NPB; if (end > NN) end = NN;

    float acc = 0.f;
    int cur = batch[start];
    if ((unsigned)cur >= NG) cur = 0;
    for (int n = start; n < end; n++) {
        int b = batch[n];
        if ((unsigned)b >= NG) b = 0;
        if (b != cur) {
            atomicAdd(&g_pool[cur * D + f], acc);
            acc = 0.f; cur = b;
        }
        acc += g_agg[(size_t)n * D + f];
    }
    atomicAdd(&g_pool[cur * D + f], acc);

    if (f == 0) {
        float c = 0.f;
        int cur2 = batch[start];
        if ((unsigned)cur2 >= NG) cur2 = 0;
        for (int n = start; n < end; n++) {
            int b = batch[n];
            if ((unsigned)b >= NG) b = 0;
            if (b != cur2) { atomicAdd(&g_cnt[cur2], c); c = 0.f; cur2 = b; }
            c += 1.0f;
        }
        atomicAdd(&g_cnt[cur2], c);
    }
}

// ---------------- final MLP + log_softmax ----------------
__global__ void k_mlp(const float* __restrict__ fc1W, const float* __restrict__ fc1b,
                      const float* __restrict__ fc2W, const float* __restrict__ fc2b,
                      float* __restrict__ out) {
    int g = blockIdx.x;
    int lane = threadIdx.x;
    __shared__ float mean[D];
    __shared__ float m1[20];
    __shared__ float z[10];
    __shared__ float lse;

    float cnt = fmaxf(g_cnt[g], 1.0f);
    for (int k = lane; k < D; k += 32) mean[k] = g_pool[g * D + k] / cnt;
    __syncwarp();

    if (lane < 20) {
        float s = fc1b[lane];
        for (int k = 0; k < D; k++) s = fmaf(mean[k], fc1W[k * 20 + lane], s);
        m1[lane] = fmaxf(s, 0.0f);
    }
    __syncwarp();

    if (lane < 10) {
        float s = fc2b[lane];
        for (int k = 0; k < 20; k++) s = fmaf(m1[k], fc2W[k * 10 + lane], s);
        z[lane] = s;
    }
    __syncwarp();

    if (lane == 0) {
        float mx = z[0];
        for (int j = 1; j < 10; j++) mx = fmaxf(mx, z[j]);
        float s = 0.f;
        for (int j = 0; j < 10; j++) s += expf(z[j] - mx);
        lse = mx + logf(s);
    }
    __syncwarp();

    if (lane < 10) out[g * 10 + lane] = z[lane] - lse;
}

// ---------------- launch ----------------
extern "C" void kernel_launch(void* const* d_in, const int* in_sizes, int n_in,
                              void* d_out, int out_size) {
    int ix = -1, iei = -1, ib = -1, iW[2] = {-1, -1}, ibias[2] = {-1, -1};
    int if1W = -1, if1b = -1, if2W = -1, if2b = -1;
    int nW = 0, nbias = 0;
    for (int i = 0; i < n_in; i++) {
        int s = in_sizes[i];
        if      (s == NN * D)            ix = i;
        else if (s == NN)                ib = i;
        else if (s == D * D && nW < 2)   iW[nW++] = i;
        else if (s == D && nbias < 2)    ibias[nbias++] = i;
        else if (s == D * 20)            if1W = i;
        else if (s == 20)                if1b = i;
        else if (s == 20 * 10)           if2W = i;
        else if (s == 10)                if2b = i;
        else if (s > NN)                 iei = i;
    }
    bool ok = (ix >= 0 && iei >= 0 && ib >= 0 && nW == 2 && nbias == 2 &&
               if1W >= 0 && if1b >= 0 && if2W >= 0 && if2b >= 0);
    if (!ok) {
        ix = 0; iei = 1; ib = 2; iW[0] = 3; ibias[0] = 4; iW[1] = 5; ibias[1] = 6;
        if1W = 7; if1b = 8; if2W = 9; if2b = 10;
    }

    const float* x     = (const float*)d_in[ix];
    const int*   ei    = (const int*)d_in[iei];
    const int*   batch = (const int*)d_in[ib];
    const float* W1   = (const float*)d_in[iW[0]];
    const float* b1   = (const float*)d_in[ibias[0]];
    const float* W2   = (const float*)d_in[iW[1]];
    const float* b2   = (const float*)d_in[ibias[1]];
    const float* fc1W = (const float*)d_in[if1W];
    const float* fc1b = (const float*)d_in[if1b];
    const float* fc2W = (const float*)d_in[if2W];
    const float* fc2b = (const float*)d_in[if2b];
    float* out = (float*)d_out;

    int E = in_sizes[iei] / 2;

    const int T = 256;
    int nb_edges  = (E + T - 1) / T;
    int nb_gemm   = (NN + BM - 1) / BM;
    int nb_gather = (int)(((size_t)NN * 32 + T - 1) / T);
    int nb_pool   = (NN + NPB - 1) / NPB;

    k_gemm_l1<<<nb_gemm, 256>>>(x, W1, ei, E);        // 0 (gemm + edge count)
    k_scan<<<1, SCAN_T>>>();                          // 1
    k_fill<<<nb_edges, T>>>(ei, E);                   // 2
    k_gather<true><<<nb_gather, T>>>(b1);             // 3  <- profiled (the unknown!)
    k_gemm_l2<<<nb_gemm, 256>>>(W2);                  // 4
    k_gather<false><<<nb_gather, T>>>(b2);            // 5
    k_pool<<<nb_pool, D>>>(batch);                    // 6
    k_mlp<<<NG, 32>>>(fc1W, fc1b, fc2W, fc2b, out);   // 7
}

// round 13
// speedup vs baseline: 1.6290x; 1.2074x over previous
#include <cuda_runtime.h>
#include <cuda_fp16.h>
#include <math.h>

#define NN 100000
#define NG 64
#define D  128
#define EMAX 2000000

// -------- scratch (device globals; no runtime allocation) --------
__device__ __half g_h  [(size_t)NN * D];   // GEMM output, fp16 (gather payload)
__device__ float  g_agg[(size_t)NN * D];   // layer-2 aggregated output (pool input)
__device__ __half g_elu[(size_t)NN * D];   // elu(layer-1 agg), fp16 = layer-2 GEMM input
__device__ float  g_dinv[NN];              // deg^{-1/2}
__device__ int    g_cnti[NN];              // per-dst edge counts (re-zeroed by k_scan)
__device__ int    g_off [NN + 1];          // CSR offsets (exact)
__device__ int    g_cur [NN];              // fill cursors
__device__ int    g_srcs[EMAX];            // CSR adjacency
__device__ float  g_pool[NG * D];
__device__ float  g_cnt [NG];

// ---------------- CSR build ----------------
__global__ void k_count(const int* __restrict__ ei, int E) {
    int e = blockIdx.x * blockDim.x + threadIdx.x;
    if (e >= E) return;
    unsigned dst = (unsigned)ei[(size_t)E + e];
    if (dst < NN) atomicAdd(&g_cnti[dst], 1);
}

#define SCAN_T 1024
__global__ void k_scan() {
    __shared__ int ssum[SCAN_T];
    int t = threadIdx.x;

    for (int i = t; i < NG * D; i += SCAN_T) g_pool[i] = 0.f;
    if (t < NG) g_cnt[t] = 0.f;

    int per = (NN + SCAN_T - 1) / SCAN_T;
    int lo = t * per, hi = lo + per; if (hi > NN) hi = NN;
    int s = 0;
    for (int i = lo; i < hi; i++) s += g_cnti[i];
    ssum[t] = s;
    __syncthreads();
    for (int ofs = 1; ofs < SCAN_T; ofs <<= 1) {
        int v = (t >= ofs) ? ssum[t - ofs] : 0;
        __syncthreads();
        ssum[t] += v;
        __syncthreads();
    }
    int run = (t == 0) ? 0 : ssum[t - 1];
    for (int i = lo; i < hi; i++) {
        int c = g_cnti[i];
        g_off[i] = run;
        g_cur[i] = run;
        g_dinv[i] = rsqrtf((float)c + 1.0f);   // +1 self loop
        g_cnti[i] = 0;                          // ready for next replay
        run += c;
    }
    if (t == SCAN_T - 1) g_off[NN] = run;
}

__global__ void k_fill(const int* __restrict__ ei, int E) {
    int e = blockIdx.x * blockDim.x + threadIdx.x;
    if (e >= E) return;
    unsigned src = (unsigned)ei[e];
    unsigned dst = (unsigned)ei[(size_t)E + e];
    if (src >= NN || dst >= NN) return;
    int pos = atomicAdd(&g_cur[dst], 1);
    if (pos < EMAX) g_srcs[pos] = (int)src;
}

// ---------------- tensor-core GEMM: g_h = half(X @ W) ---------------------
// 128x128 block tile, BK=64, 8 warps (4m x 2n), warp tile 32x64,
// mma.m16n8k16 fp16 in / fp32 acc.
#define PADA 8
#define PADW 8

template<bool FP16IN>
__device__ __forceinline__ void gemm_mma_body(const void* Xv, const float* __restrict__ W) {
    __shared__ __half sX[128][64 + PADA];    // 18.0 KB  [m][k]
    __shared__ __half sW[64][128 + PADW];    // 17.0 KB  [k][n]

    int tid  = threadIdx.x;
    int warp = tid >> 5, lane = tid & 31;
    int wm = warp >> 1, wn = warp & 1;       // 4 x 2 warp grid
    int g = lane >> 2, t = lane & 3;
    int m0 = blockIdx.x * 128;

    float acc[2][8][4];
#pragma unroll
    for (int mt = 0; mt < 2; mt++)
#pragma unroll
        for (int nt = 0; nt < 8; nt++)
#pragma unroll
            for (int r = 0; r < 4; r++) acc[mt][nt][r] = 0.f;

    for (int kt = 0; kt < 2; kt++) {
        int kbase = kt * 64;
        // ---- stage X tile (convert to fp16 if needed) ----
        if (FP16IN) {
            const __half* X = (const __half*)Xv;
#pragma unroll
            for (int i = 0; i < 8; i++) {
                int idx = tid + 256 * i;     // 0..2047
                int r   = idx >> 4;          // 0..127
                int c4  = idx & 15;          // 4-half chunk
                int row = m0 + r;
                uint2 v = make_uint2(0u, 0u);
                if (row < NN) v = *(const uint2*)(X + (size_t)row * D + kbase + c4 * 4);
                *(uint2*)&sX[r][c4 * 4] = v;
            }
        } else {
            const float* X = (const float*)Xv;
#pragma unroll
            for (int i = 0; i < 8; i++) {
                int idx = tid + 256 * i;
                int r   = idx >> 4;
                int c4  = idx & 15;
                int row = m0 + r;
                float4 v = make_float4(0.f, 0.f, 0.f, 0.f);
                if (row < NN) v = __ldg((const float4*)(X + (size_t)row * D + kbase) + c4);
                __half2 h01 = __floats2half2_rn(v.x, v.y);
                __half2 h23 = __floats2half2_rn(v.z, v.w);
                *(__half2*)&sX[r][c4 * 4]     = h01;
                *(__half2*)&sX[r][c4 * 4 + 2] = h23;
            }
        }
        // ---- stage W tile (fp32 -> fp16), [k][n] ----
#pragma unroll
        for (int i = 0; i < 8; i++) {
            int idx = tid + 256 * i;        // 0..2047
            int k   = idx >> 5;             // 0..63
            int n4  = idx & 31;             // 4-float chunk
            float4 v = __ldg((const float4*)(W + (size_t)(kbase + k) * D) + n4);
            __half2 h01 = __floats2half2_rn(v.x, v.y);
            __half2 h23 = __floats2half2_rn(v.z, v.w);
            *(__half2*)&sW[k][n4 * 4]     = h01;
            *(__half2*)&sW[k][n4 * 4 + 2] = h23;
        }
        __syncthreads();

#pragma unroll
        for (int ks = 0; ks < 4; ks++) {
            int k0 = ks * 16;
            unsigned a[2][4];
#pragma unroll
            for (int mt = 0; mt < 2; mt++) {
                int rb = wm * 32 + mt * 16;
                a[mt][0] = *(const unsigned*)&sX[rb + g    ][k0 + 2 * t];
                a[mt][1] = *(const unsigned*)&sX[rb + g + 8][k0 + 2 * t];
                a[mt][2] = *(const unsigned*)&sX[rb + g    ][k0 + 2 * t + 8];
                a[mt][3] = *(const unsigned*)&sX[rb + g + 8][k0 + 2 * t + 8];
            }
#pragma unroll
            for (int nt = 0; nt < 8; nt++) {
                int n = wn * 64 + nt * 8 + g;
                __half2 b0h = __halves2half2(sW[k0 + 2 * t    ][n], sW[k0 + 2 * t + 1][n]);
                __half2 b1h = __halves2half2(sW[k0 + 2 * t + 8][n], sW[k0 + 2 * t + 9][n]);
                unsigned b0 = *(unsigned*)&b0h;
                unsigned b1 = *(unsigned*)&b1h;
#pragma unroll
                for (int mt = 0; mt < 2; mt++) {
                    asm volatile(
                        "mma.sync.aligned.m16n8k16.row.col.f32.f16.f16.f32 "
                        "{%0,%1,%2,%3}, {%4,%5,%6,%7}, {%8,%9}, {%0,%1,%2,%3};\n"
                        : "+f"(acc[mt][nt][0]), "+f"(acc[mt][nt][1]),
                          "+f"(acc[mt][nt][2]), "+f"(acc[mt][nt][3])
                        : "r"(a[mt][0]), "r"(a[mt][1]), "r"(a[mt][2]), "r"(a[mt][3]),
                          "r"(b0), "r"(b1));
                }
            }
        }
        __syncthreads();
    }

    // ---- epilogue: fp16 store ----
#pragma unroll
    for (int mt = 0; mt < 2; mt++) {
        int r0 = m0 + wm * 32 + mt * 16 + g;
        int r1 = r0 + 8;
#pragma unroll
        for (int nt = 0; nt < 8; nt++) {
            int col = wn * 64 + nt * 8 + 2 * t;
            if (r0 < NN)
                *(__half2*)(g_h + (size_t)r0 * D + col) =
                    __floats2half2_rn(acc[mt][nt][0], acc[mt][nt][1]);
            if (r1 < NN)
                *(__half2*)(g_h + (size_t)r1 * D + col) =
                    __floats2half2_rn(acc[mt][nt][2], acc[mt][nt][3]);
        }
    }
}

__global__ __launch_bounds__(256, 2)
void k_gemm_l1(const float* __restrict__ X, const float* __restrict__ W) {
    gemm_mma_body<false>(X, W);
}

__global__ __launch_bounds__(256, 2)
void k_gemm_l2(const float* __restrict__ W) {
    gemm_mma_body<true>(g_elu, W);
}

// ---------------- CSR gather (warp/node, fp16 rows) -----------------------
// out = bias + dinv[n] * ( dinv[n]*h[n] + sum_s dinv[s]*h[s] )
__device__ __forceinline__ float4 ld_row_h(int s, int lane) {
    uint2 u = __ldg((const uint2*)(g_h + (size_t)s * D) + lane);  // 4 halves
    float2 a = __half22float2(*(__half2*)&u.x);
    float2 b = __half22float2(*(__half2*)&u.y);
    return make_float4(a.x, a.y, b.x, b.y);
}

template<bool DO_ELU>
__global__ void k_gather(const float* __restrict__ bias) {
    int node = (blockIdx.x * blockDim.x + threadIdx.x) >> 5;
    int lane = threadIdx.x & 31;
    if (node >= NN) return;

    float dv = g_dinv[node];
    float4 self = ld_row_h(node, lane);
    float4 acc = make_float4(self.x * dv, self.y * dv, self.z * dv, self.w * dv);

    int j   = g_off[node];
    int end = g_off[node + 1];
    for (; j + 4 <= end; j += 4) {
        int s0 = __ldg(&g_srcs[j + 0]);
        int s1 = __ldg(&g_srcs[j + 1]);
        int s2 = __ldg(&g_srcs[j + 2]);
        int s3 = __ldg(&g_srcs[j + 3]);
        float d0 = __ldg(&g_dinv[s0]);
        float d1 = __ldg(&g_dinv[s1]);
        float d2 = __ldg(&g_dinv[s2]);
        float d3 = __ldg(&g_dinv[s3]);
        float4 v0 = ld_row_h(s0, lane);
        float4 v1 = ld_row_h(s1, lane);
        float4 v2 = ld_row_h(s2, lane);
        float4 v3 = ld_row_h(s3, lane);
        acc.x += v0.x * d0 + v1.x * d1 + v2.x * d2 + v3.x * d3;
        acc.y += v0.y * d0 + v1.y * d1 + v2.y * d2 + v3.y * d3;
        acc.z += v0.z * d0 + v1.z * d1 + v2.z * d2 + v3.z * d3;
        acc.w += v0.w * d0 + v1.w * d1 + v2.w * d2 + v3.w * d3;
    }
    for (; j < end; j++) {
        int s = __ldg(&g_srcs[j]);
        float d = __ldg(&g_dinv[s]);
        float4 v = ld_row_h(s, lane);
        acc.x += v.x * d; acc.y += v.y * d;
        acc.z += v.z * d; acc.w += v.w * d;
    }

    float4 b = __ldg((const float4*)bias + lane);
    acc.x = b.x + dv * acc.x;
    acc.y = b.y + dv * acc.y;
    acc.z = b.z + dv * acc.z;
    acc.w = b.w + dv * acc.w;

    if (DO_ELU) {
        acc.x = acc.x > 0.f ? acc.x : expm1f(acc.x);
        acc.y = acc.y > 0.f ? acc.y : expm1f(acc.y);
        acc.z = acc.z > 0.f ? acc.z : expm1f(acc.z);
        acc.w = acc.w > 0.f ? acc.w : expm1f(acc.w);
        uint2 u;
        *(__half2*)&u.x = __floats2half2_rn(acc.x, acc.y);
        *(__half2*)&u.y = __floats2half2_rn(acc.z, acc.w);
        ((uint2*)(g_elu + (size_t)node * D))[lane] = u;
    } else {
        ((float4*)(g_agg + (size_t)node * D))[lane] = acc;
    }
}

// ---------------- pooling ----------------
#define NPB 256
__global__ void k_pool(const int* __restrict__ batch) {
    int f = threadIdx.x;
    int start = blockIdx.x * NPB;
    if (start >= NN) return;
    int end = start + NPB; if (end > NN) end = NN;

    float acc = 0.f;
    int cur = batch[start];
    if ((unsigned)cur >= NG) cur = 0;
    for (int n = start; n < end; n++) {
        int b = batch[n];
        if ((unsigned)b >= NG) b = 0;
        if (b != cur) {
            atomicAdd(&g_pool[cur * D + f], acc);
            acc = 0.f; cur = b;
        }
        acc += g_agg[(size_t)n * D + f];
    }
    atomicAdd(&g_pool[cur * D + f], acc);

    if (f == 0) {
        float c = 0.f;
        int cur2 = batch[start];
        if ((unsigned)cur2 >= NG) cur2 = 0;
        for (int n = start; n < end; n++) {
            int b = batch[n];
            if ((unsigned)b >= NG) b = 0;
            if (b != cur2) { atomicAdd(&g_cnt[cur2], c); c = 0.f; cur2 = b; }
            c += 1.0f;
        }
        atomicAdd(&g_cnt[cur2], c);
    }
}

// ---------------- final MLP + log_softmax ----------------
__global__ void k_mlp(const float* __restrict__ fc1W, const float* __restrict__ fc1b,
                      const float* __restrict__ fc2W, const float* __restrict__ fc2b,
                      float* __restrict__ out) {
    int g = blockIdx.x;
    int lane = threadIdx.x;
    __shared__ float mean[D];
    __shared__ float m1[20];
    __shared__ float z[10];
    __shared__ float lse;

    float cnt = fmaxf(g_cnt[g], 1.0f);
    for (int k = lane; k < D; k += 32) mean[k] = g_pool[g * D + k] / cnt;
    __syncwarp();

    if (lane < 20) {
        float s = fc1b[lane];
        for (int k = 0; k < D; k++) s = fmaf(mean[k], fc1W[k * 20 + lane], s);
        m1[lane] = fmaxf(s, 0.0f);
    }
    __syncwarp();

    if (lane < 10) {
        float s = fc2b[lane];
        for (int k = 0; k < 20; k++) s = fmaf(m1[k], fc2W[k * 10 + lane], s);
        z[lane] = s;
    }
    __syncwarp();

    if (lane == 0) {
        float mx = z[0];
        for (int j = 1; j < 10; j++) mx = fmaxf(mx, z[j]);
        float s = 0.f;
        for (int j = 0; j < 10; j++) s += expf(z[j] - mx);
        lse = mx + logf(s);
    }
    __syncwarp();

    if (lane < 10) out[g * 10 + lane] = z[lane] - lse;
}

// ---------------- launch ----------------
extern "C" void kernel_launch(void* const* d_in, const int* in_sizes, int n_in,
                              void* d_out, int out_size) {
    int ix = -1, iei = -1, ib = -1, iW[2] = {-1, -1}, ibias[2] = {-1, -1};
    int if1W = -1, if1b = -1, if2W = -1, if2b = -1;
    int nW = 0, nbias = 0;
    for (int i = 0; i < n_in; i++) {
        int s = in_sizes[i];
        if      (s == NN * D)            ix = i;
        else if (s == NN)                ib = i;
        else if (s == D * D && nW < 2)   iW[nW++] = i;
        else if (s == D && nbias < 2)    ibias[nbias++] = i;
        else if (s == D * 20)            if1W = i;
        else if (s == 20)                if1b = i;
        else if (s == 20 * 10)           if2W = i;
        else if (s == 10)                if2b = i;
        else if (s > NN)                 iei = i;
    }
    bool ok = (ix >= 0 && iei >= 0 && ib >= 0 && nW == 2 && nbias == 2 &&
               if1W >= 0 && if1b >= 0 && if2W >= 0 && if2b >= 0);
    if (!ok) {
        ix = 0; iei = 1; ib = 2; iW[0] = 3; ibias[0] = 4; iW[1] = 5; ibias[1] = 6;
        if1W = 7; if1b = 8; if2W = 9; if2b = 10;
    }

    const float* x     = (const float*)d_in[ix];
    const int*   ei    = (const int*)d_in[iei];
    const int*   batch = (const int*)d_in[ib];
    const float* W1   = (const float*)d_in[iW[0]];
    const float* b1   = (const float*)d_in[ibias[0]];
    const float* W2   = (const float*)d_in[iW[1]];
    const float* b2   = (const float*)d_in[ibias[1]];
    const float* fc1W = (const float*)d_in[if1W];
    const float* fc1b = (const float*)d_in[if1b];
    const float* fc2W = (const float*)d_in[if2W];
    const float* fc2b = (const float*)d_in[if2b];
    float* out = (float*)d_out;

    int E = in_sizes[iei] / 2;

    const int T = 256;
    int nb_edges  = (E + T - 1) / T;
    int nb_gemm   = (NN + 127) / 128;
    int nb_gather = (int)(((size_t)NN * 32 + T - 1) / T);
    int nb_pool   = (NN + NPB - 1) / NPB;

    k_count<<<nb_edges, T>>>(ei, E);                  // 0
    k_scan<<<1, SCAN_T>>>();                          // 1
    k_fill<<<nb_edges, T>>>(ei, E);                   // 2
    k_gemm_l1<<<nb_gemm, 256>>>(x, W1);               // 3  <- profiled (new MMA GEMM)
    k_gather<true><<<nb_gather, T>>>(b1);             // 4  -> g_elu (fp16)
    k_gemm_l2<<<nb_gemm, 256>>>(W2);                  // 5
    k_gather<false><<<nb_gather, T>>>(b2);            // 6  -> g_agg
    k_pool<<<nb_pool, D>>>(batch);                    // 7
    k_mlp<<<NG, 32>>>(fc1W, fc1b, fc2W, fc2b, out);   // 8
}

// round 15
// speedup vs baseline: 2.9552x; 1.8141x over previous
#include <cuda_runtime.h>
#include <cuda_fp16.h>
#include <stdint.h>
#include <math.h>

#define NN 100000
#define NG 64
#define D  128
#define EMAX 2000000

// -------- scratch (device globals; no runtime allocation) --------
__device__ __half g_h  [(size_t)NN * D];   // GEMM output, fp16 (gather payload)
__device__ float  g_agg[(size_t)NN * D];   // layer-2 aggregated output (pool input)
__device__ __half g_elu[(size_t)NN * D];   // elu(layer-1 agg), fp16 = layer-2 GEMM input
__device__ float  g_dinv[NN];              // deg^{-1/2}
__device__ int    g_cnti[NN];              // per-dst edge counts (re-zeroed by scan3)
__device__ int    g_off [NN + 1];          // CSR offsets (exact)
__device__ int    g_cur [NN];              // fill cursors
__device__ int    g_srcs[EMAX];            // CSR adjacency
__device__ float  g_pool[NG * D];
__device__ float  g_cnt [NG];

#define SB 1024
#define NBS ((NN + SB - 1) / SB)           // 98
__device__ int g_bsum[NBS];
__device__ int g_boff[NBS];

// ---------------- CSR build ----------------
__global__ void k_count(const int* __restrict__ ei, int E) {
    int e = blockIdx.x * blockDim.x + threadIdx.x;
    if (e >= E) return;
    unsigned dst = (unsigned)ei[(size_t)E + e];
    if (dst < NN) atomicAdd(&g_cnti[dst], 1);
}

// phase 1: per-block sums of g_cnti
__global__ void k_scan1() {
    __shared__ int sh[SB];
    int t = threadIdx.x;
    int idx = blockIdx.x * SB + t;
    sh[t] = (idx < NN) ? g_cnti[idx] : 0;
    __syncthreads();
#pragma unroll
    for (int o = SB / 2; o > 0; o >>= 1) {
        if (t < o) sh[t] += sh[t + o];
        __syncthreads();
    }
    if (t == 0) g_bsum[blockIdx.x] = sh[0];
}

// phase 2: single tiny block — scan the 98 partials; zero pool accumulators
__global__ void k_scan2() {
    __shared__ int s[128];
    int t = threadIdx.x;   // 128 threads
    for (int i = t; i < NG * D; i += 128) g_pool[i] = 0.f;
    if (t < NG) g_cnt[t] = 0.f;

    int v = (t < NBS) ? g_bsum[t] : 0;
    int orig = v;
    s[t] = v;
    __syncthreads();
#pragma unroll
    for (int o = 1; o < 128; o <<= 1) {
        int u = (t >= o) ? s[t - o] : 0;
        __syncthreads();
        s[t] += u;
        __syncthreads();
    }
    if (t < NBS) g_boff[t] = s[t] - orig;       // exclusive
    if (t == NBS - 1) g_off[NN] = s[t];          // total
}

// phase 3: block-local scan + write off/cur/dinv, reset cnti
__global__ void k_scan3() {
    __shared__ int sh[SB];
    int t = threadIdx.x;
    int idx = blockIdx.x * SB + t;
    int c = (idx < NN) ? g_cnti[idx] : 0;
    sh[t] = c;
    __syncthreads();
#pragma unroll
    for (int o = 1; o < SB; o <<= 1) {
        int u = (t >= o) ? sh[t - o] : 0;
        __syncthreads();
        sh[t] += u;
        __syncthreads();
    }
    if (idx < NN) {
        int off = sh[t] - c + g_boff[blockIdx.x];
        g_off[idx]  = off;
        g_cur[idx]  = off;
        g_dinv[idx] = rsqrtf((float)c + 1.0f);   // +1 self loop
        g_cnti[idx] = 0;                          // ready for next replay
    }
}

__global__ void k_fill(const int* __restrict__ ei, int E) {
    int e = blockIdx.x * blockDim.x + threadIdx.x;
    if (e >= E) return;
    unsigned src = (unsigned)ei[e];
    unsigned dst = (unsigned)ei[(size_t)E + e];
    if (src >= NN || dst >= NN) return;
    int pos = atomicAdd(&g_cur[dst], 1);
    if (pos < EMAX) g_srcs[pos] = (int)src;
}

// ---------------- tensor-core GEMM: g_h = half(X @ W) ---------------------
// 128x128 block tile, BK=64, 8 warps (4m x 2n), warp tile 32x64,
// mma.m16n8k16 with ldmatrix fragment loads.
#define PADA 8
#define PADW 8
#define SXW (64 + PADA)
#define SWW (128 + PADW)

#define LDSM_X4(r0, r1, r2, r3, addr) \
    asm volatile("ldmatrix.sync.aligned.m8n8.x4.shared.b16 {%0,%1,%2,%3}, [%4];" \
                 : "=r"(r0), "=r"(r1), "=r"(r2), "=r"(r3) : "r"(addr))
#define LDSM_X4T(r0, r1, r2, r3, addr) \
    asm volatile("ldmatrix.sync.aligned.m8n8.x4.trans.shared.b16 {%0,%1,%2,%3}, [%4];" \
                 : "=r"(r0), "=r"(r1), "=r"(r2), "=r"(r3) : "r"(addr))

template<bool FP16IN>
__device__ __forceinline__ void gemm_mma_body(const void* Xv, const float* __restrict__ W) {
    __shared__ __half sX[128][SXW];
    __shared__ __half sW[64][SWW];

    int tid  = threadIdx.x;
    int warp = tid >> 5, lane = tid & 31;
    int wm = warp >> 1, wn = warp & 1;       // 4 x 2 warp grid
    int g = lane >> 2, t = lane & 3;
    int m0 = blockIdx.x * 128;

    const unsigned sXs = (unsigned)__cvta_generic_to_shared(&sX[0][0]);
    const unsigned sWs = (unsigned)__cvta_generic_to_shared(&sW[0][0]);

    float acc[2][8][4];
#pragma unroll
    for (int mt = 0; mt < 2; mt++)
#pragma unroll
        for (int nt = 0; nt < 8; nt++)
#pragma unroll
            for (int r = 0; r < 4; r++) acc[mt][nt][r] = 0.f;

    for (int kt = 0; kt < 2; kt++) {
        int kbase = kt * 64;
        // ---- stage X tile ----
        if (FP16IN) {
            const __half* X = (const __half*)Xv;
#pragma unroll
            for (int i = 0; i < 8; i++) {
                int idx = tid + 256 * i;
                int r   = idx >> 4;
                int c4  = idx & 15;
                int row = m0 + r;
                uint2 v = make_uint2(0u, 0u);
                if (row < NN) v = *(const uint2*)(X + (size_t)row * D + kbase + c4 * 4);
                *(uint2*)&sX[r][c4 * 4] = v;
            }
        } else {
            const float* X = (const float*)Xv;
#pragma unroll
            for (int i = 0; i < 8; i++) {
                int idx = tid + 256 * i;
                int r   = idx >> 4;
                int c4  = idx & 15;
                int row = m0 + r;
                float4 v = make_float4(0.f, 0.f, 0.f, 0.f);
                if (row < NN) v = __ldg((const float4*)(X + (size_t)row * D + kbase) + c4);
                *(__half2*)&sX[r][c4 * 4]     = __floats2half2_rn(v.x, v.y);
                *(__half2*)&sX[r][c4 * 4 + 2] = __floats2half2_rn(v.z, v.w);
            }
        }
        // ---- stage W tile (fp32 -> fp16), [k][n] ----
#pragma unroll
        for (int i = 0; i < 8; i++) {
            int idx = tid + 256 * i;
            int k   = idx >> 5;
            int n4  = idx & 31;
            float4 v = __ldg((const float4*)(W + (size_t)(kbase + k) * D) + n4);
            *(__half2*)&sW[k][n4 * 4]     = __floats2half2_rn(v.x, v.y);
            *(__half2*)&sW[k][n4 * 4 + 2] = __floats2half2_rn(v.z, v.w);
        }
        __syncthreads();

#pragma unroll
        for (int ks = 0; ks < 4; ks++) {
            int k0 = ks * 16;
            // A fragments: ldmatrix x4 (rows rb + lane%16, col k0 + (lane/16)*8)
            unsigned a[2][4];
#pragma unroll
            for (int mt = 0; mt < 2; mt++) {
                int row  = wm * 32 + mt * 16 + (lane & 15);
                int colh = k0 + ((lane >> 4) << 3);
                unsigned ad = sXs + (unsigned)(row * SXW + colh) * 2u;
                LDSM_X4(a[mt][0], a[mt][1], a[mt][2], a[mt][3], ad);
            }
            // B fragments: ldmatrix x4 trans, 2 n-slices per issue
            unsigned bf[8][2];
#pragma unroll
            for (int q = 0; q < 4; q++) {
                int rowk = k0 + (lane & 15);
                int col  = wn * 64 + q * 16 + ((lane >> 4) << 3);
                unsigned ad = sWs + (unsigned)(rowk * SWW + col) * 2u;
                LDSM_X4T(bf[2 * q][0], bf[2 * q][1], bf[2 * q + 1][0], bf[2 * q + 1][1], ad);
            }
#pragma unroll
            for (int nt = 0; nt < 8; nt++)
#pragma unroll
                for (int mt = 0; mt < 2; mt++) {
                    asm volatile(
                        "mma.sync.aligned.m16n8k16.row.col.f32.f16.f16.f32 "
                        "{%0,%1,%2,%3}, {%4,%5,%6,%7}, {%8,%9}, {%0,%1,%2,%3};\n"
                        : "+f"(acc[mt][nt][0]), "+f"(acc[mt][nt][1]),
                          "+f"(acc[mt][nt][2]), "+f"(acc[mt][nt][3])
                        : "r"(a[mt][0]), "r"(a[mt][1]), "r"(a[mt][2]), "r"(a[mt][3]),
                          "r"(bf[nt][0]), "r"(bf[nt][1]));
                }
        }
        __syncthreads();
    }

    // ---- epilogue: fp16 store ----
#pragma unroll
    for (int mt = 0; mt < 2; mt++) {
        int r0 = m0 + wm * 32 + mt * 16 + g;
        int r1 = r0 + 8;
#pragma unroll
        for (int nt = 0; nt < 8; nt++) {
            int col = wn * 64 + nt * 8 + 2 * t;
            if (r0 < NN)
                *(__half2*)(g_h + (size_t)r0 * D + col) =
                    __floats2half2_rn(acc[mt][nt][0], acc[mt][nt][1]);
            if (r1 < NN)
                *(__half2*)(g_h + (size_t)r1 * D + col) =
                    __floats2half2_rn(acc[mt][nt][2], acc[mt][nt][3]);
        }
    }
}

__global__ __launch_bounds__(256, 2)
void k_gemm_l1(const float* __restrict__ X, const float* __restrict__ W) {
    gemm_mma_body<false>(X, W);
}

__global__ __launch_bounds__(256, 2)
void k_gemm_l2(const float* __restrict__ W) {
    gemm_mma_body<true>(g_elu, W);
}

// ---------------- CSR gather (warp/node, fp16 rows) -----------------------
__device__ __forceinline__ float4 ld_row_h(int s, int lane) {
    uint2 u = __ldg((const uint2*)(g_h + (size_t)s * D) + lane);
    float2 a = __half22float2(*(__half2*)&u.x);
    float2 b = __half22float2(*(__half2*)&u.y);
    return make_float4(a.x, a.y, b.x, b.y);
}

template<bool DO_ELU>
__global__ void k_gather(const float* __restrict__ bias) {
    int node = (blockIdx.x * blockDim.x + threadIdx.x) >> 5;
    int lane = threadIdx.x & 31;
    if (node >= NN) return;

    float dv = g_dinv[node];
    float4 self = ld_row_h(node, lane);
    float4 acc = make_float4(self.x * dv, self.y * dv, self.z * dv, self.w * dv);

    int j   = g_off[node];
    int end = g_off[node + 1];
    for (; j + 4 <= end; j += 4) {
        int s0 = __ldg(&g_srcs[j + 0]);
        int s1 = __ldg(&g_srcs[j + 1]);
        int s2 = __ldg(&g_srcs[j + 2]);
        int s3 = __ldg(&g_srcs[j + 3]);
        float d0 = __ldg(&g_dinv[s0]);
        float d1 = __ldg(&g_dinv[s1]);
        float d2 = __ldg(&g_dinv[s2]);
        float d3 = __ldg(&g_dinv[s3]);
        float4 v0 = ld_row_h(s0, lane);
        float4 v1 = ld_row_h(s1, lane);
        float4 v2 = ld_row_h(s2, lane);
        float4 v3 = ld_row_h(s3, lane);
        acc.x += v0.x * d0 + v1.x * d1 + v2.x * d2 + v3.x * d3;
        acc.y += v0.y * d0 + v1.y * d1 + v2.y * d2 + v3.y * d3;
        acc.z += v0.z * d0 + v1.z * d1 + v2.z * d2 + v3.z * d3;
        acc.w += v0.w * d0 + v1.w * d1 + v2.w * d2 + v3.w * d3;
    }
    for (; j < end; j++) {
        int s = __ldg(&g_srcs[j]);
        float d = __ldg(&g_dinv[s]);
        float4 v = ld_row_h(s, lane);
        acc.x += v.x * d; acc.y += v.y * d;
        acc.z += v.z * d; acc.w += v.w * d;
    }

    float4 b = __ldg((const float4*)bias + lane);
    acc.x = b.x + dv * acc.x;
    acc.y = b.y + dv * acc.y;
    acc.z = b.z + dv * acc.z;
    acc.w = b.w + dv * acc.w;

    if (DO_ELU) {
        acc.x = acc.x > 0.f ? acc.x : expm1f(acc.x);
        acc.y = acc.y > 0.f ? acc.y : expm1f(acc.y);
        acc.z = acc.z > 0.f ? acc.z : expm1f(acc.z);
        acc.w = acc.w > 0.f ? acc.w : expm1f(acc.w);
        uint2 u;
        *(__half2*)&u.x = __floats2half2_rn(acc.x, acc.y);
        *(__half2*)&u.y = __floats2half2_rn(acc.z, acc.w);
        ((uint2*)(g_elu + (size_t)node * D))[lane] = u;
    } else {
        ((float4*)(g_agg + (size_t)node * D))[lane] = acc;
    }
}

// ---------------- pooling ----------------
#define NPB 256
__global__ void k_pool(const int* __restrict__ batch) {
    int f = threadIdx.x;
    int start = blockIdx.x * NPB;
    if (start >= NN) return;
    int end = start + NPB; if (end > NN) end = NN;

    float acc = 0.f;
    int cur = batch[start];
    if ((unsigned)cur >= NG) cur = 0;
    for (int n = start; n < end; n++) {
        int b = batch[n];
        if ((unsigned)b >= NG) b = 0;
        if (b != cur) {
            atomicAdd(&g_pool[cur * D + f], acc);
            acc = 0.f; cur = b;
        }
        acc += g_agg[(size_t)n * D + f];
    }
    atomicAdd(&g_pool[cur * D + f], acc);

    if (f == 0) {
        float c = 0.f;
        int cur2 = batch[start];
        if ((unsigned)cur2 >= NG) cur2 = 0;
        for (int n = start; n < end; n++) {
            int b = batch[n];
            if ((unsigned)b >= NG) b = 0;
            if (b != cur2) { atomicAdd(&g_cnt[cur2], c); c = 0.f; cur2 = b; }
            c += 1.0f;
        }
        atomicAdd(&g_cnt[cur2], c);
    }
}

// ---------------- final MLP + log_softmax ----------------
__global__ void k_mlp(const float* __restrict__ fc1W, const float* __restrict__ fc1b,
                      const float* __restrict__ fc2W, const float* __restrict__ fc2b,
                      float* __restrict__ out) {
    int g = blockIdx.x;
    int lane = threadIdx.x;
    __shared__ float mean[D];
    __shared__ float m1[20];
    __shared__ float z[10];
    __shared__ float lse;

    float cnt = fmaxf(g_cnt[g], 1.0f);
    for (int k = lane; k < D; k += 32) mean[k] = g_pool[g * D + k] / cnt;
    __syncwarp();

    if (lane < 20) {
        float s = fc1b[lane];
        for (int k = 0; k < D; k++) s = fmaf(mean[k], fc1W[k * 20 + lane], s);
        m1[lane] = fmaxf(s, 0.0f);
    }
    __syncwarp();

    if (lane < 10) {
        float s = fc2b[lane];
        for (int k = 0; k < 20; k++) s = fmaf(m1[k], fc2W[k * 10 + lane], s);
        z[lane] = s;
    }
    __syncwarp();

    if (lane == 0) {
        float mx = z[0];
        for (int j = 1; j < 10; j++) mx = fmaxf(mx, z[j]);
        float s = 0.f;
        for (int j = 0; j < 10; j++) s += expf(z[j] - mx);
        lse = mx + logf(s);
    }
    __syncwarp();

    if (lane < 10) out[g * 10 + lane] = z[lane] - lse;
}

// ---------------- launch ----------------
extern "C" void kernel_launch(void* const* d_in, const int* in_sizes, int n_in,
                              void* d_out, int out_size) {
    int ix = -1, iei = -1, ib = -1, iW[2] = {-1, -1}, ibias[2] = {-1, -1};
    int if1W = -1, if1b = -1, if2W = -1, if2b = -1;
    int nW = 0, nbias = 0;
    for (int i = 0; i < n_in; i++) {
        int s = in_sizes[i];
        if      (s == NN * D)            ix = i;
        else if (s == NN)                ib = i;
        else if (s == D * D && nW < 2)   iW[nW++] = i;
        else if (s == D && nbias < 2)    ibias[nbias++] = i;
        else if (s == D * 20)            if1W = i;
        else if (s == 20)                if1b = i;
        else if (s == 20 * 10)           if2W = i;
        else if (s == 10)                if2b = i;
        else if (s > NN)                 iei = i;
    }
    bool ok = (ix >= 0 && iei >= 0 && ib >= 0 && nW == 2 && nbias == 2 &&
               if1W >= 0 && if1b >= 0 && if2W >= 0 && if2b >= 0);
    if (!ok) {
        ix = 0; iei = 1; ib = 2; iW[0] = 3; ibias[0] = 4; iW[1] = 5; ibias[1] = 6;
        if1W = 7; if1b = 8; if2W = 9; if2b = 10;
    }

    const float* x     = (const float*)d_in[ix];
    const int*   ei    = (const int*)d_in[iei];
    const int*   batch = (const int*)d_in[ib];
    const float* W1   = (const float*)d_in[iW[0]];
    const float* b1   = (const float*)d_in[ibias[0]];
    const float* W2   = (const float*)d_in[iW[1]];
    const float* b2   = (const float*)d_in[ibias[1]];
    const float* fc1W = (const float*)d_in[if1W];
    const float* fc1b = (const float*)d_in[if1b];
    const float* fc2W = (const float*)d_in[if2W];
    const float* fc2b = (const float*)d_in[if2b];
    float* out = (float*)d_out;

    int E = in_sizes[iei] / 2;

    const int T = 256;
    int nb_edges  = (E + T - 1) / T;
    int nb_gemm   = (NN + 127) / 128;
    int nb_gather = (int)(((size_t)NN * 32 + T - 1) / T);
    int nb_pool   = (NN + NPB - 1) / NPB;

    k_count<<<nb_edges, T>>>(ei, E);                  // 0
    k_scan1<<<NBS, SB>>>();                           // 1
    k_scan2<<<1, 128>>>();                            // 2
    k_gemm_l1<<<nb_gemm, 256>>>(x, W1);               // 3  <- profiled (ldmatrix GEMM)
    k_scan3<<<NBS, SB>>>();                           // 4
    k_fill<<<nb_edges, T>>>(ei, E);                   // 5
    k_gather<true><<<nb_gather, T>>>(b1);             // 6  -> g_elu (fp16)
    k_gemm_l2<<<nb_gemm, 256>>>(W2);                  // 7
    k_gather<false><<<nb_gather, T>>>(b2);            // 8  -> g_agg
    k_pool<<<nb_pool, D>>>(batch);                    // 9
    k_mlp<<<NG, 32>>>(fc1W, fc1b, fc2W, fc2b, out);   // 10
}